// round 14
// baseline (speedup 1.0000x reference)
#include <cuda_runtime.h>
#include <cuda_fp16.h>

#define B    16
#define CIN  256
#define COUT 128
#define SDIM 512
#define HOUT 128
#define PL   4420          // 65*68 padded phase plane (per co-pair, in half2 units)
#define PSTR (4*PL)
#define OTOT ((size_t)B * 64 * PSTR * 2)   // halves: [b][co/2][plane][65][68][2]

typedef unsigned long long u64;
typedef unsigned int u32;

// Scratch
__device__ float g_s[B * CIN];
__device__ __align__(128) __half g_o[OTOT];
__device__ __align__(128) __half g_wh[(size_t)B * 9 * COUT * CIN];     // [b][tap][co][ci]
__device__ __align__(128) __half g_xh[(size_t)B * 4096 * CIN];         // [b][s][ci]

__device__ __forceinline__ u32 su32(const void* p) {
    return (u32)__cvta_generic_to_shared(p);
}
__device__ __forceinline__ void cpa16s(u32 dst, const void* src) {
    asm volatile("cp.async.ca.shared.global [%0],[%1],16;\n" :: "r"(dst), "l"(src));
}
__device__ __forceinline__ void cp_commit() { asm volatile("cp.async.commit_group;"); }

__device__ __forceinline__ void ldm_x4(u32* r, u32 addr) {
    asm volatile("ldmatrix.sync.aligned.m8n8.x4.shared.b16 {%0,%1,%2,%3}, [%4];"
                 : "=r"(r[0]), "=r"(r[1]), "=r"(r[2]), "=r"(r[3]) : "r"(addr));
}
__device__ __forceinline__ void mma_f16(float* d, const u32* a, u32 b0, u32 b1) {
    asm volatile("mma.sync.aligned.m16n8k16.row.col.f32.f16.f16.f32 "
                 "{%0,%1,%2,%3},{%4,%5,%6,%7},{%8,%9},{%0,%1,%2,%3};"
                 : "+f"(d[0]), "+f"(d[1]), "+f"(d[2]), "+f"(d[3])
                 : "r"(a[0]), "r"(a[1]), "r"(a[2]), "r"(a[3]), "r"(b0), "r"(b1));
}
__device__ __forceinline__ void redadd_h2(__half* p, float a, float b) {
    __half2 h = __floats2half2_rn(a, b);
    u32 v = *(u32*)&h;
    asm volatile("red.global.add.noftz.f16x2 [%0], %1;" :: "l"(p), "r"(v) : "memory");
}

// ---------------------------------------------------------------------------
// Stage 0: zero phase planes (atomic accumulation target; graph-replay safe)
// ---------------------------------------------------------------------------
__global__ __launch_bounds__(256)
void k_zero() {
    size_t i = ((size_t)blockIdx.x * 256 + threadIdx.x) * 8;
    if (i < OTOT) *(uint4*)(g_o + i) = make_uint4(0, 0, 0, 0);
}

// ---------------------------------------------------------------------------
// Stage 1: s[b,ci] = style . mod_w^T + mod_b
// ---------------------------------------------------------------------------
__global__ void k_style(const float* __restrict__ style,
                        const float* __restrict__ mod_w,
                        const float* __restrict__ mod_b) {
    int b = blockIdx.x;
    int warp = threadIdx.x >> 5, lane = threadIdx.x & 31;
    const float* st = style + b * SDIM;
    for (int ci = warp; ci < CIN; ci += 8) {
        const float* mw = mod_w + ci * SDIM;
        float sum = 0.f;
        for (int k = lane; k < SDIM; k += 32) sum += st[k] * mw[k];
        #pragma unroll
        for (int off = 16; off; off >>= 1)
            sum += __shfl_down_sync(0xffffffffu, sum, off);
        if (lane == 0) g_s[b * CIN + ci] = sum + mod_b[ci];
    }
}

// ---------------------------------------------------------------------------
// Stage 2: modulate + demodulate -> fp16 weights [b][tap][co][ci]
// ---------------------------------------------------------------------------
__global__ void k_wprep(const float* __restrict__ weight) {
    int co = blockIdx.x, b = blockIdx.y;
    __shared__ float vbuf[CIN * 9];
    __shared__ float red[256];
    const float scale = 1.0f / 48.0f;

    float part = 0.f;
    for (int idx = threadIdx.x; idx < CIN * 9; idx += 256) {
        int ci = idx / 9;
        float v = scale * weight[co * CIN * 9 + idx] * g_s[b * CIN + ci];
        vbuf[idx] = v;
        part += v * v;
    }
    red[threadIdx.x] = part;
    __syncthreads();
    for (int s = 128; s; s >>= 1) {
        if (threadIdx.x < s) red[threadIdx.x] += red[threadIdx.x + s];
        __syncthreads();
    }
    float demod = rsqrtf(red[0] + 1e-8f);
    for (int idx = threadIdx.x; idx < CIN * 9; idx += 256) {
        int ci = idx / 9, t = idx - ci * 9;
        float v = vbuf[idx] * demod;
        g_wh[(((size_t)b * 9 + t) * COUT + co) * CIN + ci] = __float2half_rn(v);
    }
}

// ---------------------------------------------------------------------------
// Stage 2b: transpose x -> [b][spatial][ci] fp16
// ---------------------------------------------------------------------------
__global__ __launch_bounds__(256)
void k_xprep(const float* __restrict__ x) {
    __shared__ float tile[32][129];
    int sc0 = blockIdx.x * 128;
    int b   = blockIdx.y;
    int tid = threadIdx.x;
    for (int ci0 = 0; ci0 < CIN; ci0 += 32) {
        __syncthreads();
        for (int i = tid; i < 32 * 128; i += 256) {
            int cir = i >> 7, sc = i & 127;
            tile[cir][sc] = x[((size_t)(b * CIN + ci0 + cir)) * 4096 + sc0 + sc];
        }
        __syncthreads();
        for (int it = tid; it < 128 * 16; it += 256) {
            int sc = it >> 4, cu = it & 15;
            __half2 hp;
            hp.x = __float2half_rn(tile[cu * 2][sc]);
            hp.y = __float2half_rn(tile[cu * 2 + 1][sc]);
            size_t rowo = ((size_t)b * 4096 + sc0 + sc) * CIN + ci0;
            ((__half2*)(g_xh + rowo))[cu] = hp;
        }
    }
}

// ---------------------------------------------------------------------------
// Stage 3: warp-MMA GEMM, 4 warps x (64m x 64n) tiles, 128 threads.
// Block = (mtile 128 spatial, tap, b). For tap (ky,kx), element (s, co) adds
// into plane=(ky&1)*2+(kx&1) at (m,n)=(y+(ky>>1), x+(kx>>1)).
// ---------------------------------------------------------------------------
#define TILE 5120   // elems per buffer (128*40)
__global__ __launch_bounds__(128)
void k_gemm() {
    extern __shared__ __half sm[];
    __half* Ah = sm;
    __half* Bh = sm + 2 * TILE;

    int mt = blockIdx.x, t = blockIdx.y, b = blockIdx.z;
    int s0 = mt * 128;
    int tid = threadIdx.x, wid = tid >> 5, lane = tid & 31;
    int wm = wid & 1, wn = wid >> 1;

    const __half* xh = g_xh + ((size_t)b * 4096 + s0) * CIN;
    const __half* wh = g_wh + ((size_t)b * 9 + t) * COUT * CIN;

    float acc[4][8][4];
    #pragma unroll
    for (int i = 0; i < 4; i++)
        #pragma unroll
        for (int j = 0; j < 8; j++)
            #pragma unroll
            for (int k = 0; k < 4; k++) acc[i][j][k] = 0.f;

    auto issue = [&](int c, int buf) {
        int k0 = c * 32;
        #pragma unroll
        for (int i = 0; i < 4; i++) {
            int id = tid * 4 + i;
            int row = id >> 2, seg = id & 3;
            size_t go = (size_t)row * CIN + k0 + seg * 8;
            u32 so = buf * TILE + row * 40 + seg * 8;
            cpa16s(su32(Ah + so), xh + go);
            cpa16s(su32(Bh + so), wh + go);
        }
        cp_commit();
    };

    issue(0, 0);
    int cur = 0;
    #pragma unroll 1
    for (int c = 0; c < 8; c++) {
        if (c < 7) {
            issue(c + 1, cur ^ 1);
            asm volatile("cp.async.wait_group 1;");
        } else {
            asm volatile("cp.async.wait_group 0;");
        }
        __syncthreads();

        #pragma unroll
        for (int ks = 0; ks < 2; ks++) {
            u32 bh[4][4];
            #pragma unroll
            for (int ng = 0; ng < 4; ng++) {
                int row = wn * 64 + ng * 16 + (lane & 7) + ((lane & 16) ? 8 : 0);
                int col = ks * 16 + ((lane & 8) ? 8 : 0);
                ldm_x4(bh[ng], su32(Bh + cur * TILE + row * 40 + col));
            }
            #pragma unroll
            for (int mf = 0; mf < 4; mf++) {
                int row = wm * 64 + mf * 16 + (lane & 15);
                int col = ks * 16 + ((lane & 16) ? 8 : 0);
                u32 ah[4];
                ldm_x4(ah, su32(Ah + cur * TILE + row * 40 + col));
                #pragma unroll
                for (int ng = 0; ng < 4; ng++) {
                    mma_f16(acc[mf][ng * 2 + 0], ah, bh[ng][0], bh[ng][1]);
                    mma_f16(acc[mf][ng * 2 + 1], ah, bh[ng][2], bh[ng][3]);
                }
            }
        }
        __syncthreads();
        cur ^= 1;
    }

    // epilogue: packed f16x2 atomic scatter into phase plane pair-layout
    const int ky = t / 3, kx = t - ky * 3;
    const int dm = ky >> 1, dn = kx >> 1;
    const int plane = (ky & 1) * 2 + (kx & 1);
    #pragma unroll
    for (int mf = 0; mf < 4; mf++) {
        int r0 = s0 + wm * 64 + mf * 16 + (lane >> 2);
        #pragma unroll
        for (int nf = 0; nf < 8; nf++) {
            int co = wn * 64 + nf * 8 + (lane & 3) * 2;    // even
            int cp = co >> 1;
            __half* dst0 = g_o + ((size_t)(b * 64 + cp) * PSTR + (size_t)plane * PL) * 2;
            #pragma unroll
            for (int h = 0; h < 2; h++) {
                int s = r0 + h * 8;
                int off = (s >> 6) * 68 + (s & 63) + dm * 68 + dn;
                redadd_h2(dst0 + 2 * off, acc[mf][nf][h * 2], acc[mf][nf][h * 2 + 1]);
            }
        }
    }
}

// ---------------------------------------------------------------------------
// Stage 5: separable 4x4 blur from fp16 phase planes, co-pair per block.
// ---------------------------------------------------------------------------
__global__ __launch_bounds__(256)
void k_blur(float* __restrict__ out) {
    int bc2 = blockIdx.x;              // b*64 + cp
    int u0 = blockIdx.y * 16;
    int b = bc2 >> 6, cp = bc2 & 63;
    __shared__ float2 os[19][132];
    __shared__ float2 hs[19][132];
    const float bk[4] = {0.25f, 0.75f, 0.75f, 0.25f};
    const __half* src = g_o + (size_t)bc2 * PSTR * 2;

    for (int idx = threadIdx.x; idx < 19 * 132; idx += 256) {
        int r = idx / 132, c = idx - r * 132;
        int gr = u0 - 1 + r, gc = c - 1;
        float2 v = make_float2(0.f, 0.f);
        if ((unsigned)gr < 129u && (unsigned)gc < 129u) {
            int plane = ((gr & 1) << 1) | (gc & 1);
            __half2 h = *(const __half2*)(src + 2 * ((size_t)plane * PL + (gr >> 1) * 68 + (gc >> 1)));
            v = __half22float2(h);
        }
        os[r][c] = v;
    }
    __syncthreads();
    for (int idx = threadIdx.x; idx < 19 * 128; idx += 256) {
        int r = idx >> 7, v = idx & 127;
        float2 h = make_float2(0.f, 0.f);
        #pragma unroll
        for (int s = 0; s < 4; s++) {
            float2 o = os[r][v + 3 - s];
            h.x += bk[s] * o.x;
            h.y += bk[s] * o.y;
        }
        hs[r][v] = h;
    }
    __syncthreads();
    size_t ob = ((size_t)(b * COUT + cp * 2)) * HOUT * HOUT;
    for (int idx = threadIdx.x; idx < 16 * 128; idx += 256) {
        int ul = idx >> 7, v = idx & 127;
        float2 o = make_float2(0.f, 0.f);
        #pragma unroll
        for (int t = 0; t < 4; t++) {
            float2 h = hs[ul + 3 - t][v];
            o.x += bk[t] * h.x;
            o.y += bk[t] * h.y;
        }
        size_t at = ob + (size_t)(u0 + ul) * HOUT + v;
        out[at] = o.x;
        out[at + (size_t)HOUT * HOUT] = o.y;
    }
}

// ---------------------------------------------------------------------------
extern "C" void kernel_launch(void* const* d_in, const int* in_sizes, int n_in,
                              void* d_out, int out_size) {
    const float* x      = (const float*)d_in[0];
    const float* style  = (const float*)d_in[1];
    const float* weight = (const float*)d_in[2];
    const float* mod_w  = (const float*)d_in[3];
    const float* mod_b  = (const float*)d_in[4];
    float* out = (float*)d_out;

    cudaFuncSetAttribute(k_gemm, cudaFuncAttributeMaxDynamicSharedMemorySize, 4 * TILE * 2);

    k_zero<<<(unsigned)((OTOT / 8 + 255) / 256), 256>>>();
    k_style<<<B, 256>>>(style, mod_w, mod_b);
    k_xprep<<<dim3(32, B), 256>>>(x);
    k_wprep<<<dim3(COUT, B), 256>>>(weight);
    k_gemm<<<dim3(32, 9, B), 128, 4 * TILE * 2>>>();
    k_blur<<<dim3(B * 64, 8), 256>>>(out);
}

// round 15
// speedup vs baseline: 1.0607x; 1.0607x over previous
#include <cuda_runtime.h>
#include <cuda_fp16.h>

#define B    16
#define CIN  256
#define COUT 128
#define SDIM 512
#define HOUT 128
#define PL   4420          // 65*68 padded phase plane (per co-pair, in half2 units)
#define PSTR (4*PL)
#define OTOT ((size_t)B * 64 * PSTR * 2)   // halves: [b][co/2][plane][65][68][2]
#define ZBLK ((unsigned)((OTOT / 8 + 255) / 256))

typedef unsigned long long u64;
typedef unsigned int u32;

// Scratch
__device__ float g_s[B * CIN];
__device__ __align__(128) __half g_o[OTOT];
__device__ __align__(128) __half g_wh[(size_t)B * 9 * COUT * CIN];     // [b][tap][co][ci]
__device__ __align__(128) __half g_xh[(size_t)B * 4096 * CIN];         // [b][s][ci]

__device__ __forceinline__ u32 su32(const void* p) {
    return (u32)__cvta_generic_to_shared(p);
}
__device__ __forceinline__ void cpa16s(u32 dst, const void* src) {
    asm volatile("cp.async.cg.shared.global [%0],[%1],16;\n" :: "r"(dst), "l"(src));
}
__device__ __forceinline__ void cp_commit() { asm volatile("cp.async.commit_group;"); }

__device__ __forceinline__ void ldm_x4(u32* r, u32 addr) {
    asm volatile("ldmatrix.sync.aligned.m8n8.x4.shared.b16 {%0,%1,%2,%3}, [%4];"
                 : "=r"(r[0]), "=r"(r[1]), "=r"(r[2]), "=r"(r[3]) : "r"(addr));
}
__device__ __forceinline__ void mma_f16(float* d, const u32* a, u32 b0, u32 b1) {
    asm volatile("mma.sync.aligned.m16n8k16.row.col.f32.f16.f16.f32 "
                 "{%0,%1,%2,%3},{%4,%5,%6,%7},{%8,%9},{%0,%1,%2,%3};"
                 : "+f"(d[0]), "+f"(d[1]), "+f"(d[2]), "+f"(d[3])
                 : "r"(a[0]), "r"(a[1]), "r"(a[2]), "r"(a[3]), "r"(b0), "r"(b1));
}
__device__ __forceinline__ void redadd_h2(__half* p, float a, float b) {
    __half2 h = __floats2half2_rn(a, b);
    u32 v = *(u32*)&h;
    asm volatile("red.global.add.noftz.f16x2 [%0], %1;" :: "l"(p), "r"(v) : "memory");
}

// ---------------------------------------------------------------------------
// Stage 0+1: zero phase planes (blocks >=16) + style linear (blocks 0..15)
// ---------------------------------------------------------------------------
__global__ __launch_bounds__(256)
void k_style(const float* __restrict__ style,
             const float* __restrict__ mod_w,
             const float* __restrict__ mod_b) {
    if (blockIdx.x >= 16) {
        size_t i = ((size_t)(blockIdx.x - 16) * 256 + threadIdx.x) * 8;
        if (i < OTOT) *(uint4*)(g_o + i) = make_uint4(0, 0, 0, 0);
        return;
    }
    int b = blockIdx.x;
    int warp = threadIdx.x >> 5, lane = threadIdx.x & 31;
    const float* st = style + b * SDIM;
    for (int ci = warp; ci < CIN; ci += 8) {
        const float* mw = mod_w + ci * SDIM;
        float sum = 0.f;
        for (int k = lane; k < SDIM; k += 32) sum += st[k] * mw[k];
        #pragma unroll
        for (int off = 16; off; off >>= 1)
            sum += __shfl_down_sync(0xffffffffu, sum, off);
        if (lane == 0) g_s[b * CIN + ci] = sum + mod_b[ci];
    }
}

// ---------------------------------------------------------------------------
// Stage 2: modulate + demodulate -> fp16 weights [b][tap][co][ci]
// ---------------------------------------------------------------------------
__global__ void k_wprep(const float* __restrict__ weight) {
    int co = blockIdx.x, b = blockIdx.y;
    __shared__ float vbuf[CIN * 9];
    __shared__ float red[256];
    const float scale = 1.0f / 48.0f;

    float part = 0.f;
    for (int idx = threadIdx.x; idx < CIN * 9; idx += 256) {
        int ci = idx / 9;
        float v = scale * weight[co * CIN * 9 + idx] * g_s[b * CIN + ci];
        vbuf[idx] = v;
        part += v * v;
    }
    red[threadIdx.x] = part;
    __syncthreads();
    for (int s = 128; s; s >>= 1) {
        if (threadIdx.x < s) red[threadIdx.x] += red[threadIdx.x + s];
        __syncthreads();
    }
    float demod = rsqrtf(red[0] + 1e-8f);
    for (int idx = threadIdx.x; idx < CIN * 9; idx += 256) {
        int ci = idx / 9, t = idx - ci * 9;
        float v = vbuf[idx] * demod;
        g_wh[(((size_t)b * 9 + t) * COUT + co) * CIN + ci] = __float2half_rn(v);
    }
}

// ---------------------------------------------------------------------------
// Stage 2b: transpose x -> [b][spatial][ci] fp16
// ---------------------------------------------------------------------------
__global__ __launch_bounds__(256)
void k_xprep(const float* __restrict__ x) {
    __shared__ float tile[32][129];
    int sc0 = blockIdx.x * 128;
    int b   = blockIdx.y;
    int tid = threadIdx.x;
    for (int ci0 = 0; ci0 < CIN; ci0 += 32) {
        __syncthreads();
        for (int i = tid; i < 32 * 128; i += 256) {
            int cir = i >> 7, sc = i & 127;
            tile[cir][sc] = x[((size_t)(b * CIN + ci0 + cir)) * 4096 + sc0 + sc];
        }
        __syncthreads();
        for (int it = tid; it < 128 * 16; it += 256) {
            int sc = it >> 4, cu = it & 15;
            __half2 hp;
            hp.x = __float2half_rn(tile[cu * 2][sc]);
            hp.y = __float2half_rn(tile[cu * 2 + 1][sc]);
            size_t rowo = ((size_t)b * 4096 + sc0 + sc) * CIN + ci0;
            ((__half2*)(g_xh + rowo))[cu] = hp;
        }
    }
}

// ---------------------------------------------------------------------------
// Stage 3: warp-MMA GEMM (single fp16 product), 8 warps x (64m x 32n),
// 3-stage cp.async pipeline, 1 sync/chunk, packed f16x2 atomic scatter.
// ---------------------------------------------------------------------------
#define TILE 5120   // elems per buffer (128*40)
__global__ __launch_bounds__(256)
void k_gemm() {
    extern __shared__ __half sm[];
    __half* Ah = sm;               // 3 * TILE
    __half* Bh = sm + 3 * TILE;    // 3 * TILE

    int mt = blockIdx.x, t = blockIdx.y, b = blockIdx.z;
    int s0 = mt * 128;
    int tid = threadIdx.x, wid = tid >> 5, lane = tid & 31;
    int wm = wid & 1, wn = wid >> 1;

    const __half* xh = g_xh + ((size_t)b * 4096 + s0) * CIN;
    const __half* wh = g_wh + ((size_t)b * 9 + t) * COUT * CIN;

    float acc[4][4][4];
    #pragma unroll
    for (int i = 0; i < 4; i++)
        #pragma unroll
        for (int j = 0; j < 4; j++)
            #pragma unroll
            for (int k = 0; k < 4; k++) acc[i][j][k] = 0.f;

    auto issue = [&](int c, int buf) {
        int k0 = c * 32;
        #pragma unroll
        for (int i = 0; i < 2; i++) {
            int id = tid * 2 + i;
            int row = id >> 2, seg = id & 3;
            size_t go = (size_t)row * CIN + k0 + seg * 8;
            u32 so = buf * TILE + row * 40 + seg * 8;
            cpa16s(su32(Ah + so), xh + go);
            cpa16s(su32(Bh + so), wh + go);
        }
        cp_commit();
    };

    issue(0, 0);
    issue(1, 1);
    #pragma unroll 1
    for (int c = 0; c < 8; c++) {
        if (c < 7) {
            asm volatile("cp.async.wait_group 1;");
        } else {
            asm volatile("cp.async.wait_group 0;");
        }
        __syncthreads();
        if (c + 2 < 8) issue(c + 2, (c + 2) % 3);

        int cur = c % 3;
        #pragma unroll
        for (int ks = 0; ks < 2; ks++) {
            u32 bh[2][4];
            #pragma unroll
            for (int ng = 0; ng < 2; ng++) {
                int row = wn * 32 + ng * 16 + (lane & 7) + ((lane & 16) ? 8 : 0);
                int col = ks * 16 + ((lane & 8) ? 8 : 0);
                ldm_x4(bh[ng], su32(Bh + cur * TILE + row * 40 + col));
            }
            #pragma unroll
            for (int mf = 0; mf < 4; mf++) {
                int row = wm * 64 + mf * 16 + (lane & 15);
                int col = ks * 16 + ((lane & 16) ? 8 : 0);
                u32 ah[4];
                ldm_x4(ah, su32(Ah + cur * TILE + row * 40 + col));
                #pragma unroll
                for (int ng = 0; ng < 2; ng++) {
                    mma_f16(acc[mf][ng * 2 + 0], ah, bh[ng][0], bh[ng][1]);
                    mma_f16(acc[mf][ng * 2 + 1], ah, bh[ng][2], bh[ng][3]);
                }
            }
        }
    }

    // epilogue: packed f16x2 atomic scatter into phase plane pair-layout
    const int ky = t / 3, kx = t - ky * 3;
    const int dm = ky >> 1, dn = kx >> 1;
    const int plane = (ky & 1) * 2 + (kx & 1);
    #pragma unroll
    for (int mf = 0; mf < 4; mf++) {
        int r0 = s0 + wm * 64 + mf * 16 + (lane >> 2);
        #pragma unroll
        for (int nf = 0; nf < 4; nf++) {
            int co = wn * 32 + nf * 8 + (lane & 3) * 2;    // even
            int cp = co >> 1;
            __half* dst0 = g_o + ((size_t)(b * 64 + cp) * PSTR + (size_t)plane * PL) * 2;
            #pragma unroll
            for (int h = 0; h < 2; h++) {
                int s = r0 + h * 8;
                int off = (s >> 6) * 68 + (s & 63) + dm * 68 + dn;
                redadd_h2(dst0 + 2 * off, acc[mf][nf][h * 2], acc[mf][nf][h * 2 + 1]);
            }
        }
    }
}

// ---------------------------------------------------------------------------
// Stage 5: separable 4x4 blur from fp16 phase planes, co-pair per block.
// ---------------------------------------------------------------------------
__global__ __launch_bounds__(256)
void k_blur(float* __restrict__ out) {
    int bc2 = blockIdx.x;              // b*64 + cp
    int u0 = blockIdx.y * 16;
    int b = bc2 >> 6, cp = bc2 & 63;
    __shared__ float2 os[19][132];
    __shared__ float2 hs[19][132];
    const float bk[4] = {0.25f, 0.75f, 0.75f, 0.25f};
    const __half* src = g_o + (size_t)bc2 * PSTR * 2;

    for (int idx = threadIdx.x; idx < 19 * 132; idx += 256) {
        int r = idx / 132, c = idx - r * 132;
        int gr = u0 - 1 + r, gc = c - 1;
        float2 v = make_float2(0.f, 0.f);
        if ((unsigned)gr < 129u && (unsigned)gc < 129u) {
            int plane = ((gr & 1) << 1) | (gc & 1);
            __half2 h = *(const __half2*)(src + 2 * ((size_t)plane * PL + (gr >> 1) * 68 + (gc >> 1)));
            v = __half22float2(h);
        }
        os[r][c] = v;
    }
    __syncthreads();
    for (int idx = threadIdx.x; idx < 19 * 128; idx += 256) {
        int r = idx >> 7, v = idx & 127;
        float2 h = make_float2(0.f, 0.f);
        #pragma unroll
        for (int s = 0; s < 4; s++) {
            float2 o = os[r][v + 3 - s];
            h.x += bk[s] * o.x;
            h.y += bk[s] * o.y;
        }
        hs[r][v] = h;
    }
    __syncthreads();
    size_t ob = ((size_t)(b * COUT + cp * 2)) * HOUT * HOUT;
    for (int idx = threadIdx.x; idx < 16 * 128; idx += 256) {
        int ul = idx >> 7, v = idx & 127;
        float2 o = make_float2(0.f, 0.f);
        #pragma unroll
        for (int t = 0; t < 4; t++) {
            float2 h = hs[ul + 3 - t][v];
            o.x += bk[t] * h.x;
            o.y += bk[t] * h.y;
        }
        size_t at = ob + (size_t)(u0 + ul) * HOUT + v;
        out[at] = o.x;
        out[at + (size_t)HOUT * HOUT] = o.y;
    }
}

// ---------------------------------------------------------------------------
extern "C" void kernel_launch(void* const* d_in, const int* in_sizes, int n_in,
                              void* d_out, int out_size) {
    const float* x      = (const float*)d_in[0];
    const float* style  = (const float*)d_in[1];
    const float* weight = (const float*)d_in[2];
    const float* mod_w  = (const float*)d_in[3];
    const float* mod_b  = (const float*)d_in[4];
    float* out = (float*)d_out;

    cudaFuncSetAttribute(k_gemm, cudaFuncAttributeMaxDynamicSharedMemorySize, 6 * TILE * 2);

    k_style<<<16 + ZBLK, 256>>>(style, mod_w, mod_b);
    k_xprep<<<dim3(32, B), 256>>>(x);
    k_wprep<<<dim3(COUT, B), 256>>>(weight);
    k_gemm<<<dim3(32, 9, B), 256, 6 * TILE * 2>>>();
    k_blur<<<dim3(B * 64, 8), 256>>>(out);
}